// round 1
// baseline (speedup 1.0000x reference)
#include <cuda_runtime.h>
#include <math.h>

// GWD loss: mean over N rows of weighted, log1p'd, scale-normalized
// Gaussian-Wasserstein distance between 5-param rotated boxes.
// FUN='log', TAU=1.0, ALPHA=1.0, LOSS_WEIGHT=1.0
//
// Closed-form per row (pred p=(x,y,w,h,r), target t likewise):
//   xy_d   = |xy_p - xy_t|^2
//   Sigma  = R diag(w^2/4, h^2/4) R^T  (2x2 sym: a, b, d)
//   whr_d  = tr(Sp) + tr(St) - 2*sqrt(max(tr(St Sp) + 2*sqrt(det), 0))
//     with tr(St Sp) = a1*a2 + 2*b1*b2 + d1*d2
//          sqrt(det(cross)) = |wp*hp*wt*ht| / 16
//   dist   = sqrt(max(xy_d + whr_d, 0)) / (wp*wt*hp*ht)^(1/4)
//   loss_i = (1 - 1/(1 + log1p(dist))) * weight_i
//   out    = mean(loss_i)

#define NBLOCKS 1184   // 148 SMs * 8
#define NTHREADS 256

__device__ float g_partials[NBLOCKS];

__global__ __launch_bounds__(NTHREADS)
void gwd_main_kernel(const float* __restrict__ pred,
                     const float* __restrict__ target,
                     const float* __restrict__ weight,
                     int n)
{
    float acc = 0.0f;
    for (int i = blockIdx.x * NTHREADS + threadIdx.x; i < n;
         i += gridDim.x * NTHREADS)
    {
        const float* p = pred   + 5 * (long)i;
        const float* t = target + 5 * (long)i;

        float xp = p[0], yp = p[1], wp = p[2], hp = p[3], rp = p[4];
        float xt = t[0], yt = t[1], wt = t[2], ht = t[3], rt = t[4];

        float dx = xp - xt, dy = yp - yt;
        float xyd = dx * dx + dy * dy;

        float cp, sp, ct, st;
        __sincosf(rp, &sp, &cp);
        __sincosf(rt, &st, &ct);

        float w2p = 0.25f * wp * wp, h2p = 0.25f * hp * hp;
        float w2t = 0.25f * wt * wt, h2t = 0.25f * ht * ht;

        float cp2 = cp * cp, sp2 = sp * sp;
        float ct2 = ct * ct, st2 = st * st;

        float a1 = cp2 * w2p + sp2 * h2p;
        float d1 = sp2 * w2p + cp2 * h2p;
        float b1 = cp * sp * (w2p - h2p);

        float a2 = ct2 * w2t + st2 * h2t;
        float d2 = st2 * w2t + ct2 * h2t;
        float b2 = ct * st * (w2t - h2t);

        float tr_p = w2p + h2p;
        float tr_t = w2t + h2t;

        float trcross = a1 * a2 + 2.0f * b1 * b2 + d1 * d2;
        float prod4   = wp * hp * wt * ht;        // inputs are U[0,1): >= 0
        float sqdet   = fabsf(prod4) * 0.0625f;   // /16

        float inner = fmaxf(trcross + 2.0f * sqdet, 0.0f);
        float whr   = tr_p + tr_t - 2.0f * sqrtf(inner);

        float dist  = sqrtf(fmaxf(xyd + whr, 0.0f));
        float scale = sqrtf(sqrtf(fabsf(prod4)));
        dist = dist / scale;

        dist = log1pf(dist);
        float loss = 1.0f - 1.0f / (1.0f + dist);

        acc += loss * weight[i];
    }

    // block reduction: warp shuffle + shared
    __shared__ float s_warp[NTHREADS / 32];
    for (int off = 16; off > 0; off >>= 1)
        acc += __shfl_down_sync(0xFFFFFFFFu, acc, off);
    int lane = threadIdx.x & 31;
    int wid  = threadIdx.x >> 5;
    if (lane == 0) s_warp[wid] = acc;
    __syncthreads();
    if (wid == 0) {
        float v = (lane < NTHREADS / 32) ? s_warp[lane] : 0.0f;
        for (int off = 16; off > 0; off >>= 1)
            v += __shfl_down_sync(0xFFFFFFFFu, v, off);
        if (lane == 0) g_partials[blockIdx.x] = v;
    }
}

__global__ __launch_bounds__(256)
void gwd_finalize_kernel(float* __restrict__ out, float inv_n)
{
    float acc = 0.0f;
    for (int i = threadIdx.x; i < NBLOCKS; i += 256)
        acc += g_partials[i];

    __shared__ float s_warp[8];
    for (int off = 16; off > 0; off >>= 1)
        acc += __shfl_down_sync(0xFFFFFFFFu, acc, off);
    int lane = threadIdx.x & 31;
    int wid  = threadIdx.x >> 5;
    if (lane == 0) s_warp[wid] = acc;
    __syncthreads();
    if (wid == 0) {
        float v = (lane < 8) ? s_warp[lane] : 0.0f;
        for (int off = 16; off > 0; off >>= 1)
            v += __shfl_down_sync(0xFFFFFFFFu, v, off);
        if (lane == 0) out[0] = v * inv_n;
    }
}

extern "C" void kernel_launch(void* const* d_in, const int* in_sizes, int n_in,
                              void* d_out, int out_size)
{
    const float* pred   = (const float*)d_in[0];
    const float* target = (const float*)d_in[1];
    const float* weight = (const float*)d_in[2];
    float* out = (float*)d_out;

    int n = in_sizes[2];  // weight has N elements

    gwd_main_kernel<<<NBLOCKS, NTHREADS>>>(pred, target, weight, n);
    gwd_finalize_kernel<<<1, 256>>>(out, 1.0f / (float)n);
}